// round 1
// baseline (speedup 1.0000x reference)
#include <cuda_runtime.h>

#define BD 16
#define ND 4
#define NF 481
#define TT 500
#define CC 16
#define HH 32
#define NSEQ (BD * NF)              // 7696
#define PROB_ELEMS (BD * NF * TT)   // 3,848,000

// scratch: conv output x laid out [n][t][c], n = b*NF + f
__device__ float g_x[(size_t)NSEQ * TT * CC];

__device__ __forceinline__ float sigm(float x) {
    return __fdividef(1.f, 1.f + __expf(-x));
}
__device__ __forceinline__ float tanh_f(float x) {
    return __fdividef(2.f, 1.f + __expf(-2.f * x)) - 1.f;
}

// ---------------------------------------------------------------------------
// Conv stage: per frame (b,t): conv1d(4->16,k=9,pad4)+PReLU, conv1d(16->16,k=5,pad2)+PReLU
// One block = one frame. tid&15 = fixed output channel, tid>>4 = f-group, f blocked x4.
// ---------------------------------------------------------------------------
__global__ __launch_bounds__(128) void conv_kernel(
    const float* __restrict__ feat,
    const float* __restrict__ w1, const float* __restrict__ b1, const float* __restrict__ p1,
    const float* __restrict__ w2, const float* __restrict__ b2, const float* __restrict__ p2)
{
    __shared__ float s_in[ND][NF + 12];    // pad4 conv + f-block overhang, zero-filled
    __shared__ float s_mid[CC][NF + 8];    // pad2 conv + f-block overhang, zero-filled
    __shared__ float s_w1[CC * ND * 9];
    __shared__ float s_w2[CC * CC * 5];
    __shared__ float s_b1[CC], s_b2[CC];
    __shared__ float s_a[2];

    const int tid = threadIdx.x;
    const int b = blockIdx.x / TT;
    const int t = blockIdx.x % TT;

    // stage 0: zero smem tiles, load weights
    for (int i = tid; i < ND * (NF + 12); i += 128) (&s_in[0][0])[i] = 0.f;
    for (int i = tid; i < CC * (NF + 8); i += 128) (&s_mid[0][0])[i] = 0.f;
    for (int i = tid; i < CC * ND * 9; i += 128) s_w1[i] = w1[i];
    for (int i = tid; i < CC * CC * 5; i += 128) s_w2[i] = w2[i];
    if (tid < CC) { s_b1[tid] = b1[tid]; s_b2[tid] = b2[tid]; }
    if (tid == 0) { s_a[0] = p1[0]; s_a[1] = p2[0]; }
    __syncthreads();

    // stage 1: load the (4, 481) frame (strided in gmem; sectors shared via L2 across
    // concurrent t-adjacent blocks)
    for (int i = tid; i < ND * NF; i += 128) {
        const int d = i / NF, f = i - d * NF;
        s_in[d][f + 4] = feat[((size_t)(b * ND + d) * NF + f) * TT + t];
    }
    __syncthreads();

    const int c = tid & 15;
    const float a1 = s_a[0], a2 = s_a[1];

    // stage 2: conv1 + PReLU -> s_mid[c][f+2]
    {
        float wr[36];
        #pragma unroll
        for (int q = 0; q < 36; q++) wr[q] = s_w1[c * 36 + q];
        const float bias = s_b1[c];

        for (int fg = (tid >> 4); fg < 121; fg += 8) {
            const int f0 = fg * 4;
            float acc[4] = {bias, bias, bias, bias};
            #pragma unroll
            for (int d = 0; d < ND; d++) {
                float win[12];
                #pragma unroll
                for (int q = 0; q < 12; q++) win[q] = s_in[d][f0 + q];
                #pragma unroll
                for (int j = 0; j < 4; j++)
                    #pragma unroll
                    for (int k = 0; k < 9; k++)
                        acc[j] += win[j + k] * wr[d * 9 + k];
            }
            #pragma unroll
            for (int j = 0; j < 4; j++) {
                if (f0 + j < NF) {
                    const float v = acc[j];
                    s_mid[c][f0 + j + 2] = (v >= 0.f) ? v : a1 * v;
                }
            }
        }
    }
    __syncthreads();

    // stage 3: conv2 + PReLU -> g_x[(b*NF+f)*TT*CC + t*CC + c]
    {
        float wr[80];
        #pragma unroll
        for (int q = 0; q < 80; q++) wr[q] = s_w2[c * 80 + q];
        const float bias = s_b2[c];

        for (int fg = (tid >> 4); fg < 121; fg += 8) {
            const int f0 = fg * 4;
            float acc[4] = {bias, bias, bias, bias};
            #pragma unroll
            for (int ci = 0; ci < CC; ci++) {
                float win[8];
                #pragma unroll
                for (int q = 0; q < 8; q++) win[q] = s_mid[ci][f0 + q];
                #pragma unroll
                for (int j = 0; j < 4; j++)
                    #pragma unroll
                    for (int k = 0; k < 5; k++)
                        acc[j] += win[j + k] * wr[ci * 5 + k];
            }
            #pragma unroll
            for (int j = 0; j < 4; j++) {
                if (f0 + j < NF) {
                    float v = acc[j];
                    v = (v >= 0.f) ? v : a2 * v;
                    // 16 consecutive threads (c=0..15) -> contiguous 64B store group
                    g_x[((size_t)(b * NF + f0 + j) * TT + t) * CC + c] = v;
                }
            }
        }
    }
}

// ---------------------------------------------------------------------------
// GRU stage: one warp per sequence n, lane j = hidden unit j.
// Fuses the input projection (x @ W_ih^T) and FC+sigmoid epilogue.
// ---------------------------------------------------------------------------
__global__ __launch_bounds__(128) void gru_kernel(
    const float* __restrict__ h0,
    const float* __restrict__ w_ih, const float* __restrict__ w_hh,
    const float* __restrict__ b_ih, const float* __restrict__ b_hh,
    const float* __restrict__ fc_w, const float* __restrict__ fc_b,
    float* __restrict__ out)
{
    const int n = (blockIdx.x * blockDim.x + threadIdx.x) >> 5;
    const int j = threadIdx.x & 31;
    if (n >= NSEQ) return;

    // per-lane weight rows in registers
    float wir[16], wiz[16], win_[16];
    #pragma unroll
    for (int ccc = 0; ccc < 16; ccc++) {
        wir[ccc]  = w_ih[j * 16 + ccc];
        wiz[ccc]  = w_ih[(32 + j) * 16 + ccc];
        win_[ccc] = w_ih[(64 + j) * 16 + ccc];
    }
    float whr[32], whz[32], whn[32];
    #pragma unroll
    for (int k = 0; k < 32; k++) {
        whr[k] = w_hh[j * 32 + k];
        whz[k] = w_hh[(32 + j) * 32 + k];
        whn[k] = w_hh[(64 + j) * 32 + k];
    }
    const float br  = b_ih[j]      + b_hh[j];
    const float bz  = b_ih[32 + j] + b_hh[32 + j];
    const float bnx = b_ih[64 + j];
    const float bnh = b_hh[64 + j];
    const float fcw = fc_w[j];
    const float fcb = fc_b[0];

    float h = h0[n * HH + j];

    const float4* __restrict__ xp = (const float4*)(g_x + (size_t)n * TT * CC);
    float4 x0 = xp[0], x1 = xp[1], x2 = xp[2], x3 = xp[3];

    float* __restrict__ prob_out = out + (size_t)n * TT;

    for (int t = 0; t < TT; t++) {
        // prefetch next step's 16 input channels (broadcast LDG.128 x4)
        float4 q0, q1, q2, q3;
        if (t + 1 < TT) {
            const float4* np = xp + (size_t)(t + 1) * 4;
            q0 = np[0]; q1 = np[1]; q2 = np[2]; q3 = np[3];
        } else {
            q0 = q1 = q2 = q3 = make_float4(0.f, 0.f, 0.f, 0.f);
        }

        float xv[16] = {x0.x, x0.y, x0.z, x0.w, x1.x, x1.y, x1.z, x1.w,
                        x2.x, x2.y, x2.z, x2.w, x3.x, x3.y, x3.z, x3.w};

        float ar = br, az = bz, an = bnx;
        #pragma unroll
        for (int ccc = 0; ccc < 16; ccc++) {
            ar += wir[ccc] * xv[ccc];
            az += wiz[ccc] * xv[ccc];
            an += win_[ccc] * xv[ccc];
        }
        float gn = bnh;
        #pragma unroll
        for (int k = 0; k < 32; k++) {
            const float hk = __shfl_sync(0xffffffffu, h, k);
            ar += whr[k] * hk;
            az += whz[k] * hk;
            gn += whn[k] * hk;
        }

        const float r  = sigm(ar);
        const float z  = sigm(az);
        const float nn = tanh_f(an + r * gn);
        h = z * (h - nn) + nn;

        // fc + sigmoid: warp dot-product
        float p = fcw * h;
        #pragma unroll
        for (int o = 16; o > 0; o >>= 1) p += __shfl_xor_sync(0xffffffffu, p, o);
        if (j == 0) prob_out[t] = sigm(p + fcb);

        x0 = q0; x1 = q1; x2 = q2; x3 = q3;
    }

    // h_last appended after prob
    out[(size_t)PROB_ELEMS + (size_t)n * HH + j] = h;
}

extern "C" void kernel_launch(void* const* d_in, const int* in_sizes, int n_in,
                              void* d_out, int out_size) {
    const float* feat = (const float*)d_in[0];
    const float* h0   = (const float*)d_in[1];
    const float* w1   = (const float*)d_in[2];
    const float* b1   = (const float*)d_in[3];
    const float* p1   = (const float*)d_in[4];
    const float* w2   = (const float*)d_in[5];
    const float* b2   = (const float*)d_in[6];
    const float* p2   = (const float*)d_in[7];
    const float* wih  = (const float*)d_in[8];
    const float* whh  = (const float*)d_in[9];
    const float* bih  = (const float*)d_in[10];
    const float* bhh  = (const float*)d_in[11];
    const float* fcw  = (const float*)d_in[12];
    const float* fcb  = (const float*)d_in[13];
    float* out = (float*)d_out;

    conv_kernel<<<BD * TT, 128>>>(feat, w1, b1, p1, w2, b2, p2);
    gru_kernel<<<NSEQ / 4, 128>>>(h0, wih, whh, bih, bhh, fcw, fcb, out);
}

// round 2
// speedup vs baseline: 1.3549x; 1.3549x over previous
#include <cuda_runtime.h>

typedef unsigned long long u64;

#define BD 16
#define ND 4
#define NF 481
#define TT 500
#define CC 16
#define HH 32
#define NSEQ (BD * NF)              // 7696
#define PROB_ELEMS (BD * NF * TT)   // 3,848,000

// conv output x: [n][t][c], n = b*NF + f
__device__ float g_x[(size_t)NSEQ * TT * CC];
// projected gates (biases folded): [n][t][3*32]  (r[0:32], z[32:64], n[64:96])
__device__ float g_xg[(size_t)NSEQ * TT * 96];

// ---------------------------------------------------------------------------
// helpers
// ---------------------------------------------------------------------------
__device__ __forceinline__ u64 pack2(float lo, float hi) {
    u64 r; asm("mov.b64 %0, {%1,%2};" : "=l"(r) : "f"(lo), "f"(hi)); return r;
}
__device__ __forceinline__ void unpack2(u64 v, float& lo, float& hi) {
    asm("mov.b64 {%0,%1}, %2;" : "=f"(lo), "=f"(hi) : "l"(v));
}
__device__ __forceinline__ void ffma2(u64& acc, u64 a, u64 b) {
    asm("fma.rn.f32x2 %0, %1, %2, %0;" : "+l"(acc) : "l"(a), "l"(b));
}
__device__ __forceinline__ float tanha(float x) {
    float y; asm("tanh.approx.f32 %0, %1;" : "=f"(y) : "f"(x)); return y;
}
__device__ __forceinline__ float sigma(float x) {
    return fmaf(0.5f, tanha(0.5f * x), 0.5f);
}

// ---------------------------------------------------------------------------
// Conv stage (unchanged from R1): per frame (b,t): conv1(4->16,k9,p4)+PReLU,
// conv2(16->16,k5,p2)+PReLU. One block = one frame.
// ---------------------------------------------------------------------------
__global__ __launch_bounds__(128) void conv_kernel(
    const float* __restrict__ feat,
    const float* __restrict__ w1, const float* __restrict__ b1, const float* __restrict__ p1,
    const float* __restrict__ w2, const float* __restrict__ b2, const float* __restrict__ p2)
{
    __shared__ float s_in[ND][NF + 12];
    __shared__ float s_mid[CC][NF + 8];
    __shared__ float s_w1[CC * ND * 9];
    __shared__ float s_w2[CC * CC * 5];
    __shared__ float s_b1[CC], s_b2[CC];
    __shared__ float s_a[2];

    const int tid = threadIdx.x;
    const int b = blockIdx.x / TT;
    const int t = blockIdx.x % TT;

    for (int i = tid; i < ND * (NF + 12); i += 128) (&s_in[0][0])[i] = 0.f;
    for (int i = tid; i < CC * (NF + 8); i += 128) (&s_mid[0][0])[i] = 0.f;
    for (int i = tid; i < CC * ND * 9; i += 128) s_w1[i] = w1[i];
    for (int i = tid; i < CC * CC * 5; i += 128) s_w2[i] = w2[i];
    if (tid < CC) { s_b1[tid] = b1[tid]; s_b2[tid] = b2[tid]; }
    if (tid == 0) { s_a[0] = p1[0]; s_a[1] = p2[0]; }
    __syncthreads();

    for (int i = tid; i < ND * NF; i += 128) {
        const int d = i / NF, f = i - d * NF;
        s_in[d][f + 4] = feat[((size_t)(b * ND + d) * NF + f) * TT + t];
    }
    __syncthreads();

    const int c = tid & 15;
    const float a1 = s_a[0], a2 = s_a[1];

    {
        float wr[36];
        #pragma unroll
        for (int q = 0; q < 36; q++) wr[q] = s_w1[c * 36 + q];
        const float bias = s_b1[c];

        for (int fg = (tid >> 4); fg < 121; fg += 8) {
            const int f0 = fg * 4;
            float acc[4] = {bias, bias, bias, bias};
            #pragma unroll
            for (int d = 0; d < ND; d++) {
                float win[12];
                #pragma unroll
                for (int q = 0; q < 12; q++) win[q] = s_in[d][f0 + q];
                #pragma unroll
                for (int j = 0; j < 4; j++)
                    #pragma unroll
                    for (int k = 0; k < 9; k++)
                        acc[j] += win[j + k] * wr[d * 9 + k];
            }
            #pragma unroll
            for (int j = 0; j < 4; j++) {
                if (f0 + j < NF) {
                    const float v = acc[j];
                    s_mid[c][f0 + j + 2] = (v >= 0.f) ? v : a1 * v;
                }
            }
        }
    }
    __syncthreads();

    {
        float wr[80];
        #pragma unroll
        for (int q = 0; q < 80; q++) wr[q] = s_w2[c * 80 + q];
        const float bias = s_b2[c];

        for (int fg = (tid >> 4); fg < 121; fg += 8) {
            const int f0 = fg * 4;
            float acc[4] = {bias, bias, bias, bias};
            #pragma unroll
            for (int ci = 0; ci < CC; ci++) {
                float win[8];
                #pragma unroll
                for (int q = 0; q < 8; q++) win[q] = s_mid[ci][f0 + q];
                #pragma unroll
                for (int j = 0; j < 4; j++)
                    #pragma unroll
                    for (int k = 0; k < 5; k++)
                        acc[j] += win[j + k] * wr[ci * 5 + k];
            }
            #pragma unroll
            for (int j = 0; j < 4; j++) {
                if (f0 + j < NF) {
                    float v = acc[j];
                    v = (v >= 0.f) ? v : a2 * v;
                    g_x[((size_t)(b * NF + f0 + j) * TT + t) * CC + c] = v;
                }
            }
        }
    }
}

// ---------------------------------------------------------------------------
// Projection: xg[n][t][g*32+j] = b_fold + sum_c x[n][t][c] * w_ih[g*32+j][c]
// One warp per sequence n; lane j owns hidden unit j (3 gate rows in regs).
// b_ih folded for all gates; b_hh folded for r,z (n-gate's b_hh stays in GRU).
// ---------------------------------------------------------------------------
__global__ __launch_bounds__(128) void proj_kernel(
    const float* __restrict__ w_ih,
    const float* __restrict__ b_ih, const float* __restrict__ b_hh)
{
    const int n = (blockIdx.x * blockDim.x + threadIdx.x) >> 5;
    const int j = threadIdx.x & 31;
    if (n >= NSEQ) return;

    u64 wr[8], wz[8], wn[8];
    const u64* pr = (const u64*)(w_ih + (size_t)j * 16);
    const u64* pz = (const u64*)(w_ih + (size_t)(32 + j) * 16);
    const u64* pn = (const u64*)(w_ih + (size_t)(64 + j) * 16);
    #pragma unroll
    for (int p = 0; p < 8; p++) { wr[p] = pr[p]; wz[p] = pz[p]; wn[p] = pn[p]; }

    const float br = b_ih[j]      + b_hh[j];
    const float bz = b_ih[32 + j] + b_hh[32 + j];
    const float bn = b_ih[64 + j];

    const ulonglong2* __restrict__ xp = (const ulonglong2*)(g_x + (size_t)n * TT * CC);
    float* __restrict__ og = g_xg + (size_t)n * TT * 96 + j;

    for (int t = 0; t < TT; t++) {
        ulonglong2 v0 = xp[t * 4 + 0], v1 = xp[t * 4 + 1],
                   v2 = xp[t * 4 + 2], v3 = xp[t * 4 + 3];
        u64 xq[8] = {v0.x, v0.y, v1.x, v1.y, v2.x, v2.y, v3.x, v3.y};

        u64 ar = pack2(br, 0.f), az = pack2(bz, 0.f), an = pack2(bn, 0.f);
        #pragma unroll
        for (int p = 0; p < 8; p++) {
            ffma2(ar, wr[p], xq[p]);
            ffma2(az, wz[p], xq[p]);
            ffma2(an, wn[p], xq[p]);
        }
        float l0, h0_, l1, h1_, l2, h2_;
        unpack2(ar, l0, h0_); unpack2(az, l1, h1_); unpack2(an, l2, h2_);
        og[(size_t)t * 96]      = l0 + h0_;
        og[(size_t)t * 96 + 32] = l1 + h1_;
        og[(size_t)t * 96 + 64] = l2 + h2_;
    }
}

// ---------------------------------------------------------------------------
// GRU: one warp per sequence, lane j = hidden unit j. W_hh k-packed (f32x2),
// h broadcast via SMEM ping-pong, fused FC+sigmoid epilogue.
// ---------------------------------------------------------------------------
__global__ __launch_bounds__(128) void gru_kernel(
    const float* __restrict__ h0,
    const float* __restrict__ w_hh, const float* __restrict__ b_hh,
    const float* __restrict__ fc_w, const float* __restrict__ fc_b,
    float* __restrict__ out)
{
    __shared__ __align__(16) float s_h[2][4][32];

    const int w = threadIdx.x >> 5;
    const int j = threadIdx.x & 31;
    const int n = blockIdx.x * 4 + w;

    u64 whr[16], whz[16], whn[16];
    const u64* qr = (const u64*)(w_hh + (size_t)j * 32);
    const u64* qz = (const u64*)(w_hh + (size_t)(32 + j) * 32);
    const u64* qn = (const u64*)(w_hh + (size_t)(64 + j) * 32);
    #pragma unroll
    for (int p = 0; p < 16; p++) { whr[p] = qr[p]; whz[p] = qz[p]; whn[p] = qn[p]; }

    const float bhn = b_hh[64 + j];
    const float fcw = fc_w[j];
    const float fcb = fc_b[0];

    float h = h0[n * HH + j];
    s_h[0][w][j] = h;
    __syncwarp();

    const float* __restrict__ xgp = g_xg + (size_t)n * TT * 96 + j;
    float xr = xgp[0], xz = xgp[32], xn = xgp[64];

    float* __restrict__ pout = out + (size_t)n * TT;

    for (int t = 0; t < TT; t++) {
        // prefetch next step's 3 gate pre-activations (coalesced)
        float nxr = 0.f, nxz = 0.f, nxn = 0.f;
        if (t + 1 < TT) {
            const float* q = xgp + (size_t)(t + 1) * 96;
            nxr = q[0]; nxz = q[32]; nxn = q[64];
        }

        const int rb = t & 1;
        const ulonglong2* hv = (const ulonglong2*)s_h[rb][w];
        ulonglong2 a0 = hv[0], a1 = hv[1], a2 = hv[2], a3 = hv[3],
                   a4 = hv[4], a5 = hv[5], a6 = hv[6], a7 = hv[7];
        u64 hp[16] = {a0.x, a0.y, a1.x, a1.y, a2.x, a2.y, a3.x, a3.y,
                      a4.x, a4.y, a5.x, a5.y, a6.x, a6.y, a7.x, a7.y};

        u64 ar = pack2(xr, 0.f), az = pack2(xz, 0.f), an = pack2(bhn, 0.f);
        #pragma unroll
        for (int p = 0; p < 16; p++) {
            ffma2(ar, whr[p], hp[p]);
            ffma2(az, whz[p], hp[p]);
            ffma2(an, whn[p], hp[p]);
        }

        float rl, rh, zl, zh, nl, nh;
        unpack2(ar, rl, rh); unpack2(az, zl, zh); unpack2(an, nl, nh);
        const float r  = sigma(rl + rh);
        const float z  = sigma(zl + zh);
        const float gn = nl + nh;
        const float nn = tanha(fmaf(r, gn, xn));
        h = fmaf(z, h - nn, nn);

        // fc + sigmoid (chain feeds only the store, not the recurrence)
        float p_ = fcw * h;
        #pragma unroll
        for (int o = 16; o > 0; o >>= 1) p_ += __shfl_xor_sync(0xffffffffu, p_, o);
        if (j == 0) pout[t] = sigma(p_ + fcb);

        s_h[rb ^ 1][w][j] = h;
        __syncwarp();

        xr = nxr; xz = nxz; xn = nxn;
    }

    out[(size_t)PROB_ELEMS + (size_t)n * HH + j] = h;
}

extern "C" void kernel_launch(void* const* d_in, const int* in_sizes, int n_in,
                              void* d_out, int out_size) {
    const float* feat = (const float*)d_in[0];
    const float* h0   = (const float*)d_in[1];
    const float* w1   = (const float*)d_in[2];
    const float* b1   = (const float*)d_in[3];
    const float* p1   = (const float*)d_in[4];
    const float* w2   = (const float*)d_in[5];
    const float* b2   = (const float*)d_in[6];
    const float* p2   = (const float*)d_in[7];
    const float* wih  = (const float*)d_in[8];
    const float* whh  = (const float*)d_in[9];
    const float* bih  = (const float*)d_in[10];
    const float* bhh  = (const float*)d_in[11];
    const float* fcw  = (const float*)d_in[12];
    const float* fcb  = (const float*)d_in[13];
    float* out = (float*)d_out;

    conv_kernel<<<BD * TT, 128>>>(feat, w1, b1, p1, w2, b2, p2);
    proj_kernel<<<NSEQ / 4, 128>>>(wih, bih, bhh);
    gru_kernel<<<NSEQ / 4, 128>>>(h0, whh, bhh, fcw, fcb, out);
}

// round 5
// speedup vs baseline: 1.4039x; 1.0361x over previous
#include <cuda_runtime.h>

typedef unsigned long long u64;

#define BD 16
#define ND 4
#define NF 481
#define TT 500
#define CC 16
#define HH 32
#define NSEQ (BD * NF)              // 7696
#define PROB_ELEMS (BD * NF * TT)   // 3,848,000

// conv output x: [n][t][c]
__device__ float g_x[(size_t)NSEQ * TT * CC];
// projected gates (biases folded): [n][t][96] (r,z,n)
__device__ float g_xg[(size_t)NSEQ * TT * 96];
// hidden-state history: [n][t][32]
__device__ float g_h[(size_t)NSEQ * TT * HH];

// ---------------------------------------------------------------------------
// helpers
// ---------------------------------------------------------------------------
__device__ __forceinline__ u64 pack2(float lo, float hi) {
    u64 r; asm("mov.b64 %0, {%1,%2};" : "=l"(r) : "f"(lo), "f"(hi)); return r;
}
__device__ __forceinline__ void unpack2(u64 v, float& lo, float& hi) {
    asm("mov.b64 {%0,%1}, %2;" : "=f"(lo), "=f"(hi) : "l"(v));
}
__device__ __forceinline__ void ffma2(u64& acc, u64 a, u64 b) {
    asm("fma.rn.f32x2 %0, %1, %2, %0;" : "+l"(acc) : "l"(a), "l"(b));
}
__device__ __forceinline__ float tanha(float x) {
    float y; asm("tanh.approx.f32 %0, %1;" : "=f"(y) : "f"(x)); return y;
}
__device__ __forceinline__ float sigma(float x) {
    return fmaf(0.5f, tanha(0.5f * x), 0.5f);
}

// ---------------------------------------------------------------------------
// Conv stage: per frame (b,t): conv1(4->16,k9,p4)+PReLU, conv2(16->16,k5,p2)+PReLU.
// ---------------------------------------------------------------------------
__global__ __launch_bounds__(128) void conv_kernel(
    const float* __restrict__ feat,
    const float* __restrict__ w1, const float* __restrict__ b1, const float* __restrict__ p1,
    const float* __restrict__ w2, const float* __restrict__ b2, const float* __restrict__ p2)
{
    __shared__ float s_in[ND][NF + 12];
    __shared__ float s_mid[CC][NF + 8];
    __shared__ float s_w1[CC * ND * 9];
    __shared__ float s_w2[CC * CC * 5];
    __shared__ float s_b1[CC], s_b2[CC];
    __shared__ float s_a[2];

    const int tid = threadIdx.x;
    const int b = blockIdx.x / TT;
    const int t = blockIdx.x % TT;

    for (int i = tid; i < ND * (NF + 12); i += 128) (&s_in[0][0])[i] = 0.f;
    for (int i = tid; i < CC * (NF + 8); i += 128) (&s_mid[0][0])[i] = 0.f;
    for (int i = tid; i < CC * ND * 9; i += 128) s_w1[i] = w1[i];
    for (int i = tid; i < CC * CC * 5; i += 128) s_w2[i] = w2[i];
    if (tid < CC) { s_b1[tid] = b1[tid]; s_b2[tid] = b2[tid]; }
    if (tid == 0) { s_a[0] = p1[0]; s_a[1] = p2[0]; }
    __syncthreads();

    for (int i = tid; i < ND * NF; i += 128) {
        const int d = i / NF, f = i - d * NF;
        s_in[d][f + 4] = feat[((size_t)(b * ND + d) * NF + f) * TT + t];
    }
    __syncthreads();

    const int c = tid & 15;
    const float a1 = s_a[0], a2 = s_a[1];

    {
        float wr[36];
        #pragma unroll
        for (int q = 0; q < 36; q++) wr[q] = s_w1[c * 36 + q];
        const float bias = s_b1[c];

        for (int fg = (tid >> 4); fg < 121; fg += 8) {
            const int f0 = fg * 4;
            float acc[4] = {bias, bias, bias, bias};
            #pragma unroll
            for (int d = 0; d < ND; d++) {
                float win[12];
                #pragma unroll
                for (int q = 0; q < 12; q++) win[q] = s_in[d][f0 + q];
                #pragma unroll
                for (int j = 0; j < 4; j++)
                    #pragma unroll
                    for (int k = 0; k < 9; k++)
                        acc[j] += win[j + k] * wr[d * 9 + k];
            }
            #pragma unroll
            for (int j = 0; j < 4; j++) {
                if (f0 + j < NF) {
                    const float v = acc[j];
                    s_mid[c][f0 + j + 2] = (v >= 0.f) ? v : a1 * v;
                }
            }
        }
    }
    __syncthreads();

    {
        float wr[80];
        #pragma unroll
        for (int q = 0; q < 80; q++) wr[q] = s_w2[c * 80 + q];
        const float bias = s_b2[c];

        for (int fg = (tid >> 4); fg < 121; fg += 8) {
            const int f0 = fg * 4;
            float acc[4] = {bias, bias, bias, bias};
            #pragma unroll
            for (int ci = 0; ci < CC; ci++) {
                float win[8];
                #pragma unroll
                for (int q = 0; q < 8; q++) win[q] = s_mid[ci][f0 + q];
                #pragma unroll
                for (int j = 0; j < 4; j++)
                    #pragma unroll
                    for (int k = 0; k < 5; k++)
                        acc[j] += win[j + k] * wr[ci * 5 + k];
            }
            #pragma unroll
            for (int j = 0; j < 4; j++) {
                if (f0 + j < NF) {
                    float v = acc[j];
                    v = (v >= 0.f) ? v : a2 * v;
                    g_x[((size_t)(b * NF + f0 + j) * TT + t) * CC + c] = v;
                }
            }
        }
    }
}

// ---------------------------------------------------------------------------
// Projection: xg = x @ W_ih^T + folded biases. One warp per sequence.
// ---------------------------------------------------------------------------
__global__ __launch_bounds__(128) void proj_kernel(
    const float* __restrict__ w_ih,
    const float* __restrict__ b_ih, const float* __restrict__ b_hh)
{
    const int n = (blockIdx.x * blockDim.x + threadIdx.x) >> 5;
    const int j = threadIdx.x & 31;
    if (n >= NSEQ) return;

    u64 wr[8], wz[8], wn[8];
    const u64* pr = (const u64*)(w_ih + (size_t)j * 16);
    const u64* pz = (const u64*)(w_ih + (size_t)(32 + j) * 16);
    const u64* pn = (const u64*)(w_ih + (size_t)(64 + j) * 16);
    #pragma unroll
    for (int p = 0; p < 8; p++) { wr[p] = pr[p]; wz[p] = pz[p]; wn[p] = pn[p]; }

    const float br = b_ih[j]      + b_hh[j];
    const float bz = b_ih[32 + j] + b_hh[32 + j];
    const float bn = b_ih[64 + j];

    const ulonglong2* __restrict__ xp = (const ulonglong2*)(g_x + (size_t)n * TT * CC);
    float* __restrict__ og = g_xg + (size_t)n * TT * 96 + j;

    for (int t = 0; t < TT; t++) {
        ulonglong2 v0 = xp[t * 4 + 0], v1 = xp[t * 4 + 1],
                   v2 = xp[t * 4 + 2], v3 = xp[t * 4 + 3];
        u64 xq[8] = {v0.x, v0.y, v1.x, v1.y, v2.x, v2.y, v3.x, v3.y};

        u64 ar = pack2(br, 0.f), az = pack2(bz, 0.f), an = pack2(bn, 0.f);
        #pragma unroll
        for (int p = 0; p < 8; p++) {
            ffma2(ar, wr[p], xq[p]);
            ffma2(az, wz[p], xq[p]);
            ffma2(an, wn[p], xq[p]);
        }
        float l0, h0_, l1, h1_, l2, h2_;
        unpack2(ar, l0, h0_); unpack2(az, l1, h1_); unpack2(an, l2, h2_);
        og[(size_t)t * 96]      = l0 + h0_;
        og[(size_t)t * 96 + 32] = l1 + h1_;
        og[(size_t)t * 96 + 64] = l2 + h2_;
    }
}

// ---------------------------------------------------------------------------
// GRU: one warp per sequence, lane j = hidden unit j. Lean loop:
// no FC epilogue (deferred), split accumulators, h streamed to g_h.
// ---------------------------------------------------------------------------
__global__ __launch_bounds__(128, 3) void gru_kernel(
    const float* __restrict__ h0,
    const float* __restrict__ w_hh, const float* __restrict__ b_hh,
    float* __restrict__ out)
{
    __shared__ __align__(16) float s_h[2][4][32];

    const int w = threadIdx.x >> 5;
    const int j = threadIdx.x & 31;
    const int n = blockIdx.x * 4 + w;

    u64 whr[16], whz[16], whn[16];
    const u64* qr = (const u64*)(w_hh + (size_t)j * 32);
    const u64* qz = (const u64*)(w_hh + (size_t)(32 + j) * 32);
    const u64* qn = (const u64*)(w_hh + (size_t)(64 + j) * 32);
    #pragma unroll
    for (int p = 0; p < 16; p++) { whr[p] = qr[p]; whz[p] = qz[p]; whn[p] = qn[p]; }

    const float bhn = b_hh[64 + j];

    float h = h0[n * HH + j];
    s_h[0][w][j] = h;
    __syncwarp();

    const float* __restrict__ xgp = g_xg + (size_t)n * TT * 96 + j;
    float xr = xgp[0], xz = xgp[32], xn = xgp[64];

    float* __restrict__ hout = g_h + (size_t)n * TT * HH + j;

    for (int t = 0; t < TT; t++) {
        float nxr = 0.f, nxz = 0.f, nxn = 0.f;
        if (t + 1 < TT) {
            const float* q = xgp + (size_t)(t + 1) * 96;
            nxr = q[0]; nxz = q[32]; nxn = q[64];
        }

        const int rb = t & 1;
        const ulonglong2* hv = (const ulonglong2*)s_h[rb][w];
        ulonglong2 a0 = hv[0], a1 = hv[1], a2 = hv[2], a3 = hv[3],
                   a4 = hv[4], a5 = hv[5], a6 = hv[6], a7 = hv[7];
        u64 hp[16] = {a0.x, a0.y, a1.x, a1.y, a2.x, a2.y, a3.x, a3.y,
                      a4.x, a4.y, a5.x, a5.y, a6.x, a6.y, a7.x, a7.y};

        // split accumulators: 2 chains of 8 per gate
        u64 ar0 = pack2(xr, 0.f), az0 = pack2(xz, 0.f), an0 = pack2(bhn, 0.f);
        u64 ar1 = pack2(0.f, 0.f), az1 = ar1, an1 = ar1;
        #pragma unroll
        for (int p = 0; p < 8; p++) {
            ffma2(ar0, whr[2 * p],     hp[2 * p]);
            ffma2(ar1, whr[2 * p + 1], hp[2 * p + 1]);
            ffma2(az0, whz[2 * p],     hp[2 * p]);
            ffma2(az1, whz[2 * p + 1], hp[2 * p + 1]);
            ffma2(an0, whn[2 * p],     hp[2 * p]);
            ffma2(an1, whn[2 * p + 1], hp[2 * p + 1]);
        }

        float r0l, r0h, r1l, r1h, z0l, z0h, z1l, z1h, n0l, n0h, n1l, n1h;
        unpack2(ar0, r0l, r0h); unpack2(ar1, r1l, r1h);
        unpack2(az0, z0l, z0h); unpack2(az1, z1l, z1h);
        unpack2(an0, n0l, n0h); unpack2(an1, n1l, n1h);

        const float r  = sigma((r0l + r0h) + (r1l + r1h));
        const float z  = sigma((z0l + z0h) + (z1l + z1h));
        const float gn = (n0l + n0h) + (n1l + n1h);
        const float nn = tanha(fmaf(r, gn, xn));
        h = fmaf(z, h - nn, nn);

        hout[(size_t)t * HH] = h;          // coalesced 128B per warp-step
        s_h[rb ^ 1][w][j] = h;
        __syncwarp();

        xr = nxr; xz = nxz; xn = nxn;
    }

    out[(size_t)PROB_ELEMS + (size_t)n * HH + j] = h;
}

// ---------------------------------------------------------------------------
// FC epilogue: prob[n][t] = sigmoid(fc_w . h[n][t] + fc_b). Memory-bound.
// ---------------------------------------------------------------------------
__global__ __launch_bounds__(256) void fc_kernel(
    const float* __restrict__ fc_w, const float* __restrict__ fc_b,
    float* __restrict__ out)
{
    __shared__ float s_w[HH];
    if (threadIdx.x < HH) s_w[threadIdx.x] = fc_w[threadIdx.x];
    __syncthreads();

    const size_t idx = (size_t)blockIdx.x * 256 + threadIdx.x;
    if (idx >= (size_t)PROB_ELEMS) return;

    const float4* hp = (const float4*)(g_h + idx * HH);
    float acc = fc_b[0];
    #pragma unroll
    for (int q = 0; q < 8; q++) {
        const float4 v = hp[q];
        acc += v.x * s_w[q * 4] + v.y * s_w[q * 4 + 1]
             + v.z * s_w[q * 4 + 2] + v.w * s_w[q * 4 + 3];
    }
    out[idx] = sigma(acc);
}

extern "C" void kernel_launch(void* const* d_in, const int* in_sizes, int n_in,
                              void* d_out, int out_size) {
    const float* feat = (const float*)d_in[0];
    const float* h0   = (const float*)d_in[1];
    const float* w1   = (const float*)d_in[2];
    const float* b1   = (const float*)d_in[3];
    const float* p1   = (const float*)d_in[4];
    const float* w2   = (const float*)d_in[5];
    const float* b2   = (const float*)d_in[6];
    const float* p2   = (const float*)d_in[7];
    const float* wih  = (const float*)d_in[8];
    const float* whh  = (const float*)d_in[9];
    const float* bih  = (const float*)d_in[10];
    const float* bhh  = (const float*)d_in[11];
    const float* fcw  = (const float*)d_in[12];
    const float* fcb  = (const float*)d_in[13];
    float* out = (float*)d_out;

    conv_kernel<<<BD * TT, 128>>>(feat, w1, b1, p1, w2, b2, p2);
    proj_kernel<<<NSEQ / 4, 128>>>(wih, bih, bhh);
    gru_kernel<<<NSEQ / 4, 128>>>(h0, whh, bhh, out);
    fc_kernel<<<(PROB_ELEMS + 255) / 256, 256>>>(fcw, fcb, out);
}

// round 7
// speedup vs baseline: 1.7666x; 1.2583x over previous
#include <cuda_runtime.h>
#include <cuda_fp16.h>

typedef unsigned long long u64;

#define BD 16
#define ND 4
#define NF 481
#define TT 500
#define CC 16
#define HH 32
#define NSEQ (BD * NF)              // 7696
#define PROB_ELEMS (BD * NF * TT)   // 3,848,000

// conv output x: [n][t][c]
__device__ float g_x[(size_t)NSEQ * TT * CC];
// projected gates (biases folded): [n][t][96] (r,z,n); +384 pad for 4-deep prefetch
__device__ float g_xg[(size_t)NSEQ * TT * 96 + 384];
// hidden-state history (fp16): [n][t][32]
__device__ __half g_hh[(size_t)NSEQ * TT * HH];

// ---------------------------------------------------------------------------
// helpers
// ---------------------------------------------------------------------------
__device__ __forceinline__ u64 pack2(float lo, float hi) {
    u64 r; asm("mov.b64 %0, {%1,%2};" : "=l"(r) : "f"(lo), "f"(hi)); return r;
}
__device__ __forceinline__ void unpack2(u64 v, float& lo, float& hi) {
    asm("mov.b64 {%0,%1}, %2;" : "=f"(lo), "=f"(hi) : "l"(v));
}
__device__ __forceinline__ void ffma2(u64& acc, u64 a, u64 b) {
    asm("fma.rn.f32x2 %0, %1, %2, %0;" : "+l"(acc) : "l"(a), "l"(b));
}
__device__ __forceinline__ float tanha(float x) {
    float y; asm("tanh.approx.f32 %0, %1;" : "=f"(y) : "f"(x)); return y;
}
__device__ __forceinline__ float sigma(float x) {
    return fmaf(0.5f, tanha(0.5f * x), 0.5f);
}

// ---------------------------------------------------------------------------
// Conv stage: per frame (b,t): conv1(4->16,k9,p4)+PReLU, conv2(16->16,k5,p2)+PReLU.
// ---------------------------------------------------------------------------
__global__ __launch_bounds__(128) void conv_kernel(
    const float* __restrict__ feat,
    const float* __restrict__ w1, const float* __restrict__ b1, const float* __restrict__ p1,
    const float* __restrict__ w2, const float* __restrict__ b2, const float* __restrict__ p2)
{
    __shared__ float s_in[ND][NF + 12];
    __shared__ float s_mid[CC][NF + 8];
    __shared__ float s_w1[CC * ND * 9];
    __shared__ float s_w2[CC * CC * 5];
    __shared__ float s_b1[CC], s_b2[CC];
    __shared__ float s_a[2];

    const int tid = threadIdx.x;
    const int b = blockIdx.x / TT;
    const int t = blockIdx.x % TT;

    for (int i = tid; i < ND * (NF + 12); i += 128) (&s_in[0][0])[i] = 0.f;
    for (int i = tid; i < CC * (NF + 8); i += 128) (&s_mid[0][0])[i] = 0.f;
    for (int i = tid; i < CC * ND * 9; i += 128) s_w1[i] = w1[i];
    for (int i = tid; i < CC * CC * 5; i += 128) s_w2[i] = w2[i];
    if (tid < CC) { s_b1[tid] = b1[tid]; s_b2[tid] = b2[tid]; }
    if (tid == 0) { s_a[0] = p1[0]; s_a[1] = p2[0]; }
    __syncthreads();

    for (int i = tid; i < ND * NF; i += 128) {
        const int d = i / NF, f = i - d * NF;
        s_in[d][f + 4] = feat[((size_t)(b * ND + d) * NF + f) * TT + t];
    }
    __syncthreads();

    const int c = tid & 15;
    const float a1 = s_a[0], a2 = s_a[1];

    {
        float wr[36];
        #pragma unroll
        for (int q = 0; q < 36; q++) wr[q] = s_w1[c * 36 + q];
        const float bias = s_b1[c];

        for (int fg = (tid >> 4); fg < 121; fg += 8) {
            const int f0 = fg * 4;
            float acc[4] = {bias, bias, bias, bias};
            #pragma unroll
            for (int d = 0; d < ND; d++) {
                float win[12];
                #pragma unroll
                for (int q = 0; q < 12; q++) win[q] = s_in[d][f0 + q];
                #pragma unroll
                for (int j = 0; j < 4; j++)
                    #pragma unroll
                    for (int k = 0; k < 9; k++)
                        acc[j] += win[j + k] * wr[d * 9 + k];
            }
            #pragma unroll
            for (int j = 0; j < 4; j++) {
                if (f0 + j < NF) {
                    const float v = acc[j];
                    s_mid[c][f0 + j + 2] = (v >= 0.f) ? v : a1 * v;
                }
            }
        }
    }
    __syncthreads();

    {
        float wr[80];
        #pragma unroll
        for (int q = 0; q < 80; q++) wr[q] = s_w2[c * 80 + q];
        const float bias = s_b2[c];

        for (int fg = (tid >> 4); fg < 121; fg += 8) {
            const int f0 = fg * 4;
            float acc[4] = {bias, bias, bias, bias};
            #pragma unroll
            for (int ci = 0; ci < CC; ci++) {
                float win[8];
                #pragma unroll
                for (int q = 0; q < 8; q++) win[q] = s_mid[ci][f0 + q];
                #pragma unroll
                for (int j = 0; j < 4; j++)
                    #pragma unroll
                    for (int k = 0; k < 5; k++)
                        acc[j] += win[j + k] * wr[ci * 5 + k];
            }
            #pragma unroll
            for (int j = 0; j < 4; j++) {
                if (f0 + j < NF) {
                    float v = acc[j];
                    v = (v >= 0.f) ? v : a2 * v;
                    g_x[((size_t)(b * NF + f0 + j) * TT + t) * CC + c] = v;
                }
            }
        }
    }
}

// ---------------------------------------------------------------------------
// Projection: xg = x @ W_ih^T + folded biases. One warp per sequence.
// ---------------------------------------------------------------------------
__global__ __launch_bounds__(128) void proj_kernel(
    const float* __restrict__ w_ih,
    const float* __restrict__ b_ih, const float* __restrict__ b_hh)
{
    const int n = (blockIdx.x * blockDim.x + threadIdx.x) >> 5;
    const int j = threadIdx.x & 31;
    if (n >= NSEQ) return;

    u64 wr[8], wz[8], wn[8];
    const u64* pr = (const u64*)(w_ih + (size_t)j * 16);
    const u64* pz = (const u64*)(w_ih + (size_t)(32 + j) * 16);
    const u64* pn = (const u64*)(w_ih + (size_t)(64 + j) * 16);
    #pragma unroll
    for (int p = 0; p < 8; p++) { wr[p] = pr[p]; wz[p] = pz[p]; wn[p] = pn[p]; }

    const float br = b_ih[j]      + b_hh[j];
    const float bz = b_ih[32 + j] + b_hh[32 + j];
    const float bn = b_ih[64 + j];

    const ulonglong2* __restrict__ xp = (const ulonglong2*)(g_x + (size_t)n * TT * CC);
    float* __restrict__ og = g_xg + (size_t)n * TT * 96 + j;

    for (int t = 0; t < TT; t++) {
        ulonglong2 v0 = xp[t * 4 + 0], v1 = xp[t * 4 + 1],
                   v2 = xp[t * 4 + 2], v3 = xp[t * 4 + 3];
        u64 xq[8] = {v0.x, v0.y, v1.x, v1.y, v2.x, v2.y, v3.x, v3.y};

        u64 ar = pack2(br, 0.f), az = pack2(bz, 0.f), an = pack2(bn, 0.f);
        #pragma unroll
        for (int p = 0; p < 8; p++) {
            ffma2(ar, wr[p], xq[p]);
            ffma2(az, wz[p], xq[p]);
            ffma2(an, wn[p], xq[p]);
        }
        float l0, h0_, l1, h1_, l2, h2_;
        unpack2(ar, l0, h0_); unpack2(az, l1, h1_); unpack2(an, l2, h2_);
        og[(size_t)t * 96]      = l0 + h0_;
        og[(size_t)t * 96 + 32] = l1 + h1_;
        og[(size_t)t * 96 + 64] = l2 + h2_;
    }
}

// ---------------------------------------------------------------------------
// GRU: one warp per sequence, lane j = hidden unit j. 4-deep xg prefetch ring
// (registers, compile-time slots), h streamed to g_hh as fp16.
// ---------------------------------------------------------------------------
__global__ __launch_bounds__(128, 3) void gru_kernel(
    const float* __restrict__ h0,
    const float* __restrict__ w_hh, const float* __restrict__ b_hh,
    float* __restrict__ out)
{
    __shared__ __align__(16) float s_h[2][4][32];

    const int w = threadIdx.x >> 5;
    const int j = threadIdx.x & 31;
    const int n = blockIdx.x * 4 + w;

    u64 whr[16], whz[16], whn[16];
    const u64* qr = (const u64*)(w_hh + (size_t)j * 32);
    const u64* qz = (const u64*)(w_hh + (size_t)(32 + j) * 32);
    const u64* qn = (const u64*)(w_hh + (size_t)(64 + j) * 32);
    #pragma unroll
    for (int p = 0; p < 16; p++) { whr[p] = qr[p]; whz[p] = qz[p]; whn[p] = qn[p]; }

    const float bhn = b_hh[64 + j];

    float h = h0[n * HH + j];
    s_h[0][w][j] = h;
    __syncwarp();

    const float* __restrict__ xgp = g_xg + (size_t)n * TT * 96 + j;
    __half* __restrict__ hout = g_hh + (size_t)n * TT * HH + j;

    // 4-deep prefetch ring
    float bufR[4], bufZ[4], bufN[4];
    #pragma unroll
    for (int p = 0; p < 4; p++) {
        const float* q = xgp + (size_t)p * 96;
        bufR[p] = q[0]; bufZ[p] = q[32]; bufN[p] = q[64];
    }

#define GRU_STEP(S)                                                            \
    {                                                                          \
        const float xr = bufR[S], xz = bufZ[S], xn = bufN[S];                  \
        {   /* prefetch t = tb + 4 + S (array padded past TT) */               \
            const float* q = xgp + (size_t)(tb + 4 + (S)) * 96;                \
            bufR[S] = q[0]; bufZ[S] = q[32]; bufN[S] = q[64];                  \
        }                                                                      \
        const ulonglong2* hv = (const ulonglong2*)s_h[(S) & 1][w];             \
        ulonglong2 a0 = hv[0], a1 = hv[1], a2 = hv[2], a3 = hv[3],             \
                   a4 = hv[4], a5 = hv[5], a6 = hv[6], a7 = hv[7];             \
        u64 hp[16] = {a0.x, a0.y, a1.x, a1.y, a2.x, a2.y, a3.x, a3.y,          \
                      a4.x, a4.y, a5.x, a5.y, a6.x, a6.y, a7.x, a7.y};         \
        u64 ar0 = pack2(xr, 0.f), az0 = pack2(xz, 0.f), an0 = pack2(bhn, 0.f); \
        u64 ar1 = pack2(0.f, 0.f), az1 = ar1, an1 = ar1;                       \
        _Pragma("unroll")                                                      \
        for (int p = 0; p < 8; p++) {                                          \
            ffma2(ar0, whr[2 * p],     hp[2 * p]);                             \
            ffma2(ar1, whr[2 * p + 1], hp[2 * p + 1]);                         \
            ffma2(az0, whz[2 * p],     hp[2 * p]);                             \
            ffma2(az1, whz[2 * p + 1], hp[2 * p + 1]);                         \
            ffma2(an0, whn[2 * p],     hp[2 * p]);                             \
            ffma2(an1, whn[2 * p + 1], hp[2 * p + 1]);                         \
        }                                                                      \
        float r0l, r0h, r1l, r1h, z0l, z0h, z1l, z1h, n0l, n0h, n1l, n1h;      \
        unpack2(ar0, r0l, r0h); unpack2(ar1, r1l, r1h);                        \
        unpack2(az0, z0l, z0h); unpack2(az1, z1l, z1h);                        \
        unpack2(an0, n0l, n0h); unpack2(an1, n1l, n1h);                        \
        const float r  = sigma((r0l + r0h) + (r1l + r1h));                     \
        const float z  = sigma((z0l + z0h) + (z1l + z1h));                     \
        const float gn = (n0l + n0h) + (n1l + n1h);                            \
        const float nn = tanha(fmaf(r, gn, xn));                               \
        h = fmaf(z, h - nn, nn);                                               \
        hout[(size_t)(tb + (S)) * HH] = __float2half_rn(h);                    \
        s_h[((S) & 1) ^ 1][w][j] = h;                                          \
        __syncwarp();                                                          \
    }

    for (int tb = 0; tb < TT; tb += 4) {
        GRU_STEP(0)
        GRU_STEP(1)
        GRU_STEP(2)
        GRU_STEP(3)
    }
#undef GRU_STEP

    out[(size_t)PROB_ELEMS + (size_t)n * HH + j] = h;
}

// ---------------------------------------------------------------------------
// FC epilogue: prob[n][t] = sigmoid(fc_w . h[n][t] + fc_b). Memory-bound,
// reads fp16 h history (64B per thread).
// ---------------------------------------------------------------------------
__global__ __launch_bounds__(256) void fc_kernel(
    const float* __restrict__ fc_w, const float* __restrict__ fc_b,
    float* __restrict__ out)
{
    __shared__ float s_w[HH];
    if (threadIdx.x < HH) s_w[threadIdx.x] = fc_w[threadIdx.x];
    __syncthreads();

    const size_t idx = (size_t)blockIdx.x * 256 + threadIdx.x;
    if (idx >= (size_t)PROB_ELEMS) return;

    const uint4* hp = (const uint4*)(g_hh + idx * HH);
    float acc = fc_b[0];
    #pragma unroll
    for (int q = 0; q < 4; q++) {
        const uint4 u = hp[q];
        const unsigned uu[4] = {u.x, u.y, u.z, u.w};
        #pragma unroll
        for (int m = 0; m < 4; m++) {
            const float2 v = __half22float2(*(const __half2*)&uu[m]);
            acc += v.x * s_w[q * 8 + m * 2] + v.y * s_w[q * 8 + m * 2 + 1];
        }
    }
    out[idx] = sigma(acc);
}

extern "C" void kernel_launch(void* const* d_in, const int* in_sizes, int n_in,
                              void* d_out, int out_size) {
    const float* feat = (const float*)d_in[0];
    const float* h0   = (const float*)d_in[1];
    const float* w1   = (const float*)d_in[2];
    const float* b1   = (const float*)d_in[3];
    const float* p1   = (const float*)d_in[4];
    const float* w2   = (const float*)d_in[5];
    const float* b2   = (const float*)d_in[6];
    const float* p2   = (const float*)d_in[7];
    const float* wih  = (const float*)d_in[8];
    const float* whh  = (const float*)d_in[9];
    const float* bih  = (const float*)d_in[10];
    const float* bhh  = (const float*)d_in[11];
    const float* fcw  = (const float*)d_in[12];
    const float* fcb  = (const float*)d_in[13];
    float* out = (float*)d_out;

    conv_kernel<<<BD * TT, 128>>>(feat, w1, b1, p1, w2, b2, p2);
    proj_kernel<<<NSEQ / 4, 128>>>(wih, bih, bhh);
    gru_kernel<<<NSEQ / 4, 128>>>(h0, whh, bhh, out);
    fc_kernel<<<(PROB_ELEMS + 255) / 256, 256>>>(fcw, fcb, out);
}

// round 8
// speedup vs baseline: 1.8365x; 1.0396x over previous
#include <cuda_runtime.h>
#include <cuda_fp16.h>

typedef unsigned long long u64;

#define BD 16
#define ND 4
#define NF 481
#define TT 500
#define CC 16
#define HH 32
#define NSEQ (BD * NF)              // 7696
#define PROB_ELEMS (BD * NF * TT)   // 3,848,000

// conv output x: [n][t][c]
__device__ float g_x[(size_t)NSEQ * TT * CC];
// projected gates, fp16 (biases folded): [n][t][96] halfs:
//   [0:64)  = interleaved (r[j], z[j]) as half2 at half-offset 2j
//   [64:96) = n[j]
// +768 halfs pad for 4-deep prefetch overrun
__device__ __half g_xgh[(size_t)NSEQ * TT * 96 + 768];
// hidden-state history (fp16): [n][t][32]
__device__ __half g_hh[(size_t)NSEQ * TT * HH];

// ---------------------------------------------------------------------------
// helpers
// ---------------------------------------------------------------------------
__device__ __forceinline__ u64 pack2(float lo, float hi) {
    u64 r; asm("mov.b64 %0, {%1,%2};" : "=l"(r) : "f"(lo), "f"(hi)); return r;
}
__device__ __forceinline__ void unpack2(u64 v, float& lo, float& hi) {
    asm("mov.b64 {%0,%1}, %2;" : "=f"(lo), "=f"(hi) : "l"(v));
}
__device__ __forceinline__ void ffma2(u64& acc, u64 a, u64 b) {
    asm("fma.rn.f32x2 %0, %1, %2, %0;" : "+l"(acc) : "l"(a), "l"(b));
}
__device__ __forceinline__ float tanha(float x) {
    float y; asm("tanh.approx.f32 %0, %1;" : "=f"(y) : "f"(x)); return y;
}
__device__ __forceinline__ float sigma(float x) {
    return fmaf(0.5f, tanha(0.5f * x), 0.5f);
}

// ---------------------------------------------------------------------------
// Conv stage (unchanged): per frame (b,t).
// ---------------------------------------------------------------------------
__global__ __launch_bounds__(128) void conv_kernel(
    const float* __restrict__ feat,
    const float* __restrict__ w1, const float* __restrict__ b1, const float* __restrict__ p1,
    const float* __restrict__ w2, const float* __restrict__ b2, const float* __restrict__ p2)
{
    __shared__ float s_in[ND][NF + 12];
    __shared__ float s_mid[CC][NF + 8];
    __shared__ float s_w1[CC * ND * 9];
    __shared__ float s_w2[CC * CC * 5];
    __shared__ float s_b1[CC], s_b2[CC];
    __shared__ float s_a[2];

    const int tid = threadIdx.x;
    const int b = blockIdx.x / TT;
    const int t = blockIdx.x % TT;

    for (int i = tid; i < ND * (NF + 12); i += 128) (&s_in[0][0])[i] = 0.f;
    for (int i = tid; i < CC * (NF + 8); i += 128) (&s_mid[0][0])[i] = 0.f;
    for (int i = tid; i < CC * ND * 9; i += 128) s_w1[i] = w1[i];
    for (int i = tid; i < CC * CC * 5; i += 128) s_w2[i] = w2[i];
    if (tid < CC) { s_b1[tid] = b1[tid]; s_b2[tid] = b2[tid]; }
    if (tid == 0) { s_a[0] = p1[0]; s_a[1] = p2[0]; }
    __syncthreads();

    for (int i = tid; i < ND * NF; i += 128) {
        const int d = i / NF, f = i - d * NF;
        s_in[d][f + 4] = feat[((size_t)(b * ND + d) * NF + f) * TT + t];
    }
    __syncthreads();

    const int c = tid & 15;
    const float a1 = s_a[0], a2 = s_a[1];

    {
        float wr[36];
        #pragma unroll
        for (int q = 0; q < 36; q++) wr[q] = s_w1[c * 36 + q];
        const float bias = s_b1[c];

        for (int fg = (tid >> 4); fg < 121; fg += 8) {
            const int f0 = fg * 4;
            float acc[4] = {bias, bias, bias, bias};
            #pragma unroll
            for (int d = 0; d < ND; d++) {
                float win[12];
                #pragma unroll
                for (int q = 0; q < 12; q++) win[q] = s_in[d][f0 + q];
                #pragma unroll
                for (int j = 0; j < 4; j++)
                    #pragma unroll
                    for (int k = 0; k < 9; k++)
                        acc[j] += win[j + k] * wr[d * 9 + k];
            }
            #pragma unroll
            for (int j = 0; j < 4; j++) {
                if (f0 + j < NF) {
                    const float v = acc[j];
                    s_mid[c][f0 + j + 2] = (v >= 0.f) ? v : a1 * v;
                }
            }
        }
    }
    __syncthreads();

    {
        float wr[80];
        #pragma unroll
        for (int q = 0; q < 80; q++) wr[q] = s_w2[c * 80 + q];
        const float bias = s_b2[c];

        for (int fg = (tid >> 4); fg < 121; fg += 8) {
            const int f0 = fg * 4;
            float acc[4] = {bias, bias, bias, bias};
            #pragma unroll
            for (int ci = 0; ci < CC; ci++) {
                float win[8];
                #pragma unroll
                for (int q = 0; q < 8; q++) win[q] = s_mid[ci][f0 + q];
                #pragma unroll
                for (int j = 0; j < 4; j++)
                    #pragma unroll
                    for (int k = 0; k < 5; k++)
                        acc[j] += win[j + k] * wr[ci * 5 + k];
            }
            #pragma unroll
            for (int j = 0; j < 4; j++) {
                if (f0 + j < NF) {
                    float v = acc[j];
                    v = (v >= 0.f) ? v : a2 * v;
                    g_x[((size_t)(b * NF + f0 + j) * TT + t) * CC + c] = v;
                }
            }
        }
    }
}

// ---------------------------------------------------------------------------
// Projection: xg = x @ W_ih^T + folded biases, stored fp16.
// Lane j stores (r,z) as one half2 and n as one half.
// ---------------------------------------------------------------------------
__global__ __launch_bounds__(128) void proj_kernel(
    const float* __restrict__ w_ih,
    const float* __restrict__ b_ih, const float* __restrict__ b_hh)
{
    const int n = (blockIdx.x * blockDim.x + threadIdx.x) >> 5;
    const int j = threadIdx.x & 31;
    if (n >= NSEQ) return;

    u64 wr[8], wz[8], wn[8];
    const u64* pr = (const u64*)(w_ih + (size_t)j * 16);
    const u64* pz = (const u64*)(w_ih + (size_t)(32 + j) * 16);
    const u64* pn = (const u64*)(w_ih + (size_t)(64 + j) * 16);
    #pragma unroll
    for (int p = 0; p < 8; p++) { wr[p] = pr[p]; wz[p] = pz[p]; wn[p] = pn[p]; }

    const float br = b_ih[j]      + b_hh[j];
    const float bz = b_ih[32 + j] + b_hh[32 + j];
    const float bn = b_ih[64 + j];

    const ulonglong2* __restrict__ xp = (const ulonglong2*)(g_x + (size_t)n * TT * CC);
    __half* __restrict__ og = g_xgh + (size_t)n * TT * 96;

    for (int t = 0; t < TT; t++) {
        ulonglong2 v0 = xp[t * 4 + 0], v1 = xp[t * 4 + 1],
                   v2 = xp[t * 4 + 2], v3 = xp[t * 4 + 3];
        u64 xq[8] = {v0.x, v0.y, v1.x, v1.y, v2.x, v2.y, v3.x, v3.y};

        u64 ar = pack2(br, 0.f), az = pack2(bz, 0.f), an = pack2(bn, 0.f);
        #pragma unroll
        for (int p = 0; p < 8; p++) {
            ffma2(ar, wr[p], xq[p]);
            ffma2(az, wz[p], xq[p]);
            ffma2(an, wn[p], xq[p]);
        }
        float l0, h0_, l1, h1_, l2, h2_;
        unpack2(ar, l0, h0_); unpack2(az, l1, h1_); unpack2(an, l2, h2_);

        __half* ot = og + (size_t)t * 96;
        ((__half2*)ot)[j] = __floats2half2_rn(l0 + h0_, l1 + h1_);  // (r, z)
        ot[64 + j] = __float2half_rn(l2 + h2_);                      // n
    }
}

// ---------------------------------------------------------------------------
// GRU: one warp per sequence, lane j = hidden unit j. 4-deep fp16 xg prefetch
// ring (2 LDGs/step), h streamed to g_hh as fp16.
// ---------------------------------------------------------------------------
__global__ __launch_bounds__(128, 3) void gru_kernel(
    const float* __restrict__ h0,
    const float* __restrict__ w_hh, const float* __restrict__ b_hh,
    float* __restrict__ out)
{
    __shared__ __align__(16) float s_h[2][4][32];

    const int w = threadIdx.x >> 5;
    const int j = threadIdx.x & 31;
    const int n = blockIdx.x * 4 + w;

    u64 whr[16], whz[16], whn[16];
    const u64* qr = (const u64*)(w_hh + (size_t)j * 32);
    const u64* qz = (const u64*)(w_hh + (size_t)(32 + j) * 32);
    const u64* qn = (const u64*)(w_hh + (size_t)(64 + j) * 32);
    #pragma unroll
    for (int p = 0; p < 16; p++) { whr[p] = qr[p]; whz[p] = qz[p]; whn[p] = qn[p]; }

    const float bhn = b_hh[64 + j];

    float h = h0[n * HH + j];
    s_h[0][w][j] = h;
    __syncwarp();

    const __half* __restrict__ xgp = g_xgh + (size_t)n * TT * 96;
    __half* __restrict__ hout = g_hh + (size_t)n * TT * HH + j;

    // 4-deep prefetch ring (raw bits)
    __half2 bufRZ[4];
    __half  bufN[4];
    #pragma unroll
    for (int p = 0; p < 4; p++) {
        const __half* q = xgp + (size_t)p * 96;
        bufRZ[p] = ((const __half2*)q)[j];
        bufN[p]  = q[64 + j];
    }

#define GRU_STEP(S)                                                            \
    {                                                                          \
        const float2 xrz = __half22float2(bufRZ[S]);                           \
        const float xn = __half2float(bufN[S]);                                \
        {   /* prefetch t = tb + 4 + S (array padded past TT) */               \
            const __half* q = xgp + (size_t)(tb + 4 + (S)) * 96;               \
            bufRZ[S] = ((const __half2*)q)[j];                                 \
            bufN[S]  = q[64 + j];                                              \
        }                                                                      \
        const ulonglong2* hv = (const ulonglong2*)s_h[(S) & 1][w];             \
        ulonglong2 a0 = hv[0], a1 = hv[1], a2 = hv[2], a3 = hv[3],             \
                   a4 = hv[4], a5 = hv[5], a6 = hv[6], a7 = hv[7];             \
        u64 hp[16] = {a0.x, a0.y, a1.x, a1.y, a2.x, a2.y, a3.x, a3.y,          \
                      a4.x, a4.y, a5.x, a5.y, a6.x, a6.y, a7.x, a7.y};         \
        u64 ar0 = pack2(xrz.x, 0.f), az0 = pack2(xrz.y, 0.f),                  \
            an0 = pack2(bhn, 0.f);                                             \
        u64 ar1 = pack2(0.f, 0.f), az1 = ar1, an1 = ar1;                       \
        _Pragma("unroll")                                                      \
        for (int p = 0; p < 8; p++) {                                          \
            ffma2(ar0, whr[2 * p],     hp[2 * p]);                             \
            ffma2(ar1, whr[2 * p + 1], hp[2 * p + 1]);                         \
            ffma2(az0, whz[2 * p],     hp[2 * p]);                             \
            ffma2(az1, whz[2 * p + 1], hp[2 * p + 1]);                         \
            ffma2(an0, whn[2 * p],     hp[2 * p]);                             \
            ffma2(an1, whn[2 * p + 1], hp[2 * p + 1]);                         \
        }                                                                      \
        float r0l, r0h, r1l, r1h, z0l, z0h, z1l, z1h, n0l, n0h, n1l, n1h;      \
        unpack2(ar0, r0l, r0h); unpack2(ar1, r1l, r1h);                        \
        unpack2(az0, z0l, z0h); unpack2(az1, z1l, z1h);                        \
        unpack2(an0, n0l, n0h); unpack2(an1, n1l, n1h);                        \
        const float r  = sigma((r0l + r0h) + (r1l + r1h));                     \
        const float z  = sigma((z0l + z0h) + (z1l + z1h));                     \
        const float gn = (n0l + n0h) + (n1l + n1h);                            \
        const float nn = tanha(fmaf(r, gn, xn));                               \
        h = fmaf(z, h - nn, nn);                                               \
        hout[(size_t)(tb + (S)) * HH] = __float2half_rn(h);                    \
        s_h[((S) & 1) ^ 1][w][j] = h;                                          \
        __syncwarp();                                                          \
    }

    for (int tb = 0; tb < TT; tb += 4) {
        GRU_STEP(0)
        GRU_STEP(1)
        GRU_STEP(2)
        GRU_STEP(3)
    }
#undef GRU_STEP

    out[(size_t)PROB_ELEMS + (size_t)n * HH + j] = h;
}

// ---------------------------------------------------------------------------
// FC epilogue (unchanged): prob[n][t] = sigmoid(fc_w . h[n][t] + fc_b).
// ---------------------------------------------------------------------------
__global__ __launch_bounds__(256) void fc_kernel(
    const float* __restrict__ fc_w, const float* __restrict__ fc_b,
    float* __restrict__ out)
{
    __shared__ float s_w[HH];
    if (threadIdx.x < HH) s_w[threadIdx.x] = fc_w[threadIdx.x];
    __syncthreads();

    const size_t idx = (size_t)blockIdx.x * 256 + threadIdx.x;
    if (idx >= (size_t)PROB_ELEMS) return;

    const uint4* hp = (const uint4*)(g_hh + idx * HH);
    float acc = fc_b[0];
    #pragma unroll
    for (int q = 0; q < 4; q++) {
        const uint4 u = hp[q];
        const unsigned uu[4] = {u.x, u.y, u.z, u.w};
        #pragma unroll
        for (int m = 0; m < 4; m++) {
            const float2 v = __half22float2(*(const __half2*)&uu[m]);
            acc += v.x * s_w[q * 8 + m * 2] + v.y * s_w[q * 8 + m * 2 + 1];
        }
    }
    out[idx] = sigma(acc);
}

extern "C" void kernel_launch(void* const* d_in, const int* in_sizes, int n_in,
                              void* d_out, int out_size) {
    const float* feat = (const float*)d_in[0];
    const float* h0   = (const float*)d_in[1];
    const float* w1   = (const float*)d_in[2];
    const float* b1   = (const float*)d_in[3];
    const float* p1   = (const float*)d_in[4];
    const float* w2   = (const float*)d_in[5];
    const float* b2   = (const float*)d_in[6];
    const float* p2   = (const float*)d_in[7];
    const float* wih  = (const float*)d_in[8];
    const float* whh  = (const float*)d_in[9];
    const float* bih  = (const float*)d_in[10];
    const float* bhh  = (const float*)d_in[11];
    const float* fcw  = (const float*)d_in[12];
    const float* fcb  = (const float*)d_in[13];
    float* out = (float*)d_out;

    conv_kernel<<<BD * TT, 128>>>(feat, w1, b1, p1, w2, b2, p2);
    proj_kernel<<<NSEQ / 4, 128>>>(wih, bih, bhh);
    gru_kernel<<<NSEQ / 4, 128>>>(h0, whh, bhh, out);
    fc_kernel<<<(PROB_ELEMS + 255) / 256, 256>>>(fcw, fcb, out);
}